// round 6
// baseline (speedup 1.0000x reference)
#include <cuda_runtime.h>
#include <cuda_bf16.h>
#include <cstdint>

#define STX 132      // xs-kernel smem stride (proven)
#define ATS 136      // main A stride in bf16 (272B ≡ 16 mod 128 -> conflict-free ldmatrix rows)

// Scratch for x_s = x @ Wx^T + bx
__device__ float g_xs[65536 * 128];

__device__ __forceinline__ uint32_t f2tf32(float f) {
    uint32_t r; asm volatile("cvt.rna.tf32.f32 %0, %1;" : "=r"(r) : "f"(f)); return r;
}
__device__ __forceinline__ void mma_tf32_frag(float c[4], const uint32_t a[4], const uint32_t b[2]) {
    asm volatile(
        "mma.sync.aligned.m16n8k8.row.col.f32.tf32.tf32.f32 "
        "{%0,%1,%2,%3}, {%4,%5,%6,%7}, {%8,%9}, {%0,%1,%2,%3};"
        : "+f"(c[0]), "+f"(c[1]), "+f"(c[2]), "+f"(c[3])
        : "r"(a[0]), "r"(a[1]), "r"(a[2]), "r"(a[3]), "r"(b[0]), "r"(b[1]));
}
__device__ __forceinline__ void mma_bf16(float c[4], const uint32_t a[4], const uint32_t b[2]) {
    asm volatile(
        "mma.sync.aligned.m16n8k16.row.col.f32.bf16.bf16.f32 "
        "{%0,%1,%2,%3}, {%4,%5,%6,%7}, {%8,%9}, {%0,%1,%2,%3};"
        : "+f"(c[0]), "+f"(c[1]), "+f"(c[2]), "+f"(c[3])
        : "r"(a[0]), "r"(a[1]), "r"(a[2]), "r"(a[3]), "r"(b[0]), "r"(b[1]));
}
__device__ __forceinline__ void ldmatrix_x4(uint32_t a[4], uint32_t saddr) {
    asm volatile("ldmatrix.sync.aligned.m8n8.x4.shared.b16 {%0,%1,%2,%3}, [%4];"
                 : "=r"(a[0]), "=r"(a[1]), "=r"(a[2]), "=r"(a[3]) : "r"(saddr));
}
__device__ __forceinline__ uint32_t pack_bf16(float lo, float hi) {
    __nv_bfloat162 v = __floats2bfloat162_rn(lo, hi);
    return *reinterpret_cast<uint32_t*>(&v);
}

// ---------------------------------------------------------------------------
// Kernel 1: x_s = x @ Wx^T + bx  (tf32, unchanged — proven)
// ---------------------------------------------------------------------------
__global__ __launch_bounds__(256) void xs_kernel(
    const float* __restrict__ x, const float* __restrict__ Wx,
    const float* __restrict__ bx, int N)
{
    extern __shared__ float smem[];
    float* sW  = smem;
    float* sA  = sW + 128 * STX;
    float* sbx = sA + 128 * STX;
    const int tid = threadIdx.x;
    const int tileBase = blockIdx.x * 128;

    for (int i = tid; i < 128 * 128; i += 256) {
        int d = i >> 7, e = i & 127;
        ((uint32_t*)sW)[d * STX + e] = f2tf32(Wx[i]);
    }
    for (int i = tid; i < 128 * 128; i += 256) {
        int r = i >> 7, e = i & 127;
        int node = tileBase + r;
        float v = (node < N) ? x[node * 128 + e] : 0.f;
        ((uint32_t*)sA)[r * STX + e] = f2tf32(v);
    }
    if (tid < 128) sbx[tid] = bx[tid];
    __syncthreads();

    const int w = tid >> 5, lane = tid & 31;
    const int lg = lane >> 2, lc = lane & 3;
    const int wm = w >> 1, wn = w & 1;

    float acc[2][8][4];
#pragma unroll
    for (int mi = 0; mi < 2; mi++)
#pragma unroll
        for (int ni = 0; ni < 8; ni++)
#pragma unroll
            for (int j = 0; j < 4; j++) acc[mi][ni][j] = 0.f;

    const uint32_t* uA = (const uint32_t*)sA;
    const uint32_t* uW = (const uint32_t*)sW;
#pragma unroll 4
    for (int ks = 0; ks < 16; ks++) {
        const int e0 = ks * 8;
        uint32_t afr[2][4];
#pragma unroll
        for (int mi = 0; mi < 2; mi++) {
            int r = wm * 32 + mi * 16 + lg;
            afr[mi][0] = uA[r * STX + e0 + lc];
            afr[mi][1] = uA[(r + 8) * STX + e0 + lc];
            afr[mi][2] = uA[r * STX + e0 + 4 + lc];
            afr[mi][3] = uA[(r + 8) * STX + e0 + 4 + lc];
        }
#pragma unroll
        for (int ni = 0; ni < 8; ni++) {
            int c0 = wn * 64 + ni * 8;
            uint32_t bfr[2];
            bfr[0] = uW[(c0 + lg) * STX + e0 + lc];
            bfr[1] = uW[(c0 + lg) * STX + e0 + 4 + lc];
            mma_tf32_frag(acc[0][ni], afr[0], bfr);
            mma_tf32_frag(acc[1][ni], afr[1], bfr);
        }
    }
#pragma unroll
    for (int mi = 0; mi < 2; mi++)
#pragma unroll
        for (int rh = 0; rh < 2; rh++) {
            int r = wm * 32 + mi * 16 + rh * 8 + lg;
            int node = tileBase + r;
            if (node < N) {
#pragma unroll
                for (int ni = 0; ni < 8; ni++)
#pragma unroll
                    for (int cc = 0; cc < 2; cc++) {
                        int d = wn * 64 + ni * 8 + 2 * lc + cc;
                        g_xs[node * 128 + d] = acc[mi][ni][rh * 2 + cc] + sbx[d];
                    }
            }
        }
}

// ---------------------------------------------------------------------------
// Main kernel: persistent, 256 threads, 2 CTAs/SM, 2 barriers per tile.
// 8 warps = 2(wm:M32) x 4(wn:N32), K=128, bf16 m16n8k16 canonical layout.
// Wn B-fragments in regs; A via ldmatrix.x4; per-warp redundant softmax
// with attn in registers (lane = k); shfl-broadcast output.
// ---------------------------------------------------------------------------
__global__ __launch_bounds__(256, 2) void gnn_main_kernel(
    const float* __restrict__ x_nb, const float* __restrict__ weight,
    const float* __restrict__ Wn, const float* __restrict__ bn,
    const float* __restrict__ Ww, const float* __restrict__ bw,
    const float* __restrict__ Wl,
    float* __restrict__ out, int N, int numTiles)
{
    __shared__ __align__(16) __nv_bfloat16 sA[64 * ATS];   // 17408 B
    __shared__ float sxs[256];     // 2 nodes x 128
    __shared__ float swt[64];      // 2 nodes x 32
    __shared__ __align__(16) float spart[256];   // [row 0..63][wn 0..3]
    __shared__ float scb[128];     // bn + bw
    __shared__ float sWw[128];
    __shared__ float sWl[128];

    const int tid  = threadIdx.x;
    const int w    = tid >> 5, lane = tid & 31;
    const int lg   = lane >> 2, lc = lane & 3;
    const int wm   = w >> 2;     // 0..1
    const int wn   = w & 3;      // 0..3

    if (tid < 128) {
        scb[tid] = bn[tid] + bw[tid];
        sWw[tid] = Ww[tid];
        sWl[tid] = Wl[tid];
    }

    // One-time Wn B-fragment preload, canonical m16n8k16 layout:
    // b0 = B[k=2lc,2lc+1][n=lg], b1 = B[k=2lc+8,2lc+9][n=lg] per k16-slice ks.
    uint32_t breg[8][4][2];
#pragma unroll
    for (int ks = 0; ks < 8; ks++)
#pragma unroll
        for (int ni = 0; ni < 4; ni++) {
            const float* src = Wn + (size_t)(wn * 32 + ni * 8 + lg) * 128 + ks * 16 + 2 * lc;
            const float2 v0 = *(const float2*)(src);
            const float2 v1 = *(const float2*)(src + 8);
            breg[ks][ni][0] = pack_bf16(v0.x, v0.y);
            breg[ks][ni][1] = pack_bf16(v1.x, v1.y);
        }

    // ldmatrix per-lane row addresses (two m16 tiles per warp)
    const uint32_t sAsh = (uint32_t)__cvta_generic_to_shared(sA);
    uint32_t aAddr[2];
#pragma unroll
    for (int mi = 0; mi < 2; mi++)
        aAddr[mi] = sAsh + (uint32_t)(((wm * 32 + mi * 16 + (lane & 15)) * ATS
                                       + (lane >> 4) * 8) * 2);

    const long rowMax = (long)N * 32 - 1;
    const int grid = gridDim.x;

    for (int t = blockIdx.x; t < numTiles; t += grid) {
        // ---- load tile: 64 rows x 128 fp32 -> bf16 smem (STS.64) ----
        {
            float4 v[8];
            const long r0 = (long)t * 64;
#pragma unroll
            for (int u = 0; u < 8; u++) {
                const int qi = tid + u * 256;
                long gr = r0 + (qi >> 5);
                if (gr > rowMax) gr = rowMax;
                v[u] = __ldg((const float4*)x_nb + gr * 32 + (qi & 31));
            }
#pragma unroll
            for (int u = 0; u < 8; u++) {
                const int qi = tid + u * 256;
                const int row = qi >> 5, c4 = qi & 31;
                uint2 p;
                p.x = pack_bf16(v[u].x, v[u].y);
                p.y = pack_bf16(v[u].z, v[u].w);
                *(uint2*)(sA + row * ATS + c4 * 4) = p;
            }
            if (tid < 64) {
                long node = (long)t * 2 + (tid >> 5); if (node > N - 1) node = N - 1;
                ((float4*)sxs)[tid] = __ldg((const float4*)g_xs + node * 32 + (tid & 31));
            } else if (tid < 80) {
                const int j = tid - 64;
                long wi = (long)t * 16 + j;
                const long wmaxq = (long)N * 8 - 1; if (wi > wmaxq) wi = wmaxq;
                ((float4*)swt)[j] = __ldg((const float4*)weight + wi);
            }
        }
        __syncthreads();   // sync1: tile visible; also fences prior-tile spart reads

        // ---- GEMM: warp M32 x N32, K=128, A via ldmatrix, B in regs ----
        float acc[2][4][4];
#pragma unroll
        for (int mi = 0; mi < 2; mi++)
#pragma unroll
            for (int ni = 0; ni < 4; ni++)
#pragma unroll
                for (int j = 0; j < 4; j++) acc[mi][ni][j] = 0.f;

#pragma unroll
        for (int ks = 0; ks < 8; ks++) {
            uint32_t a[2][4];
            ldmatrix_x4(a[0], aAddr[0] + ks * 32);
            ldmatrix_x4(a[1], aAddr[1] + ks * 32);
#pragma unroll
            for (int ni = 0; ni < 4; ni++) {
                mma_bf16(acc[0][ni], a[0], breg[ks][ni]);
                mma_bf16(acc[1][ni], a[1], breg[ks][ni]);
            }
        }

        // ---- scores: h = n_s + x_s + (bn+bw) + weight*Ww ; leaky(0.1) ; dot Wl ----
#pragma unroll
        for (int mi = 0; mi < 2; mi++)
#pragma unroll
            for (int rh = 0; rh < 2; rh++) {
                const int r = wm * 32 + mi * 16 + rh * 8 + lg;   // 0..63
                const int node = r >> 5, k = r & 31;
                const float wgt = swt[node * 32 + k];
                float p = 0.f;
#pragma unroll
                for (int ni = 0; ni < 4; ni++)
#pragma unroll
                    for (int cc = 0; cc < 2; cc++) {
                        const int d = wn * 32 + ni * 8 + 2 * lc + cc;
                        float h = acc[mi][ni][rh * 2 + cc] + sxs[node * 128 + d]
                                + fmaf(wgt, sWw[d], scb[d]);
                        h = fmaxf(h, 0.f) + 0.1f * fminf(h, 0.f);
                        p = fmaf(sWl[d], h, p);
                    }
                p += __shfl_xor_sync(0xffffffffu, p, 1);
                p += __shfl_xor_sync(0xffffffffu, p, 2);
                if (lc == 0) spart[r * 4 + wn] = p;
            }
        __syncthreads();   // sync2: spart complete; sA reads done

        // ---- per-warp softmax (node = w>>2, lane = k); attn in registers ----
        float attn;
        {
            const int node = w >> 2;
            const float4 q = *(const float4*)(spart + (node * 32 + lane) * 4);
            float s = (q.x + q.y) + (q.z + q.w);
            float m = s;
#pragma unroll
            for (int o = 16; o; o >>= 1) m = fmaxf(m, __shfl_xor_sync(0xffffffffu, m, o));
            const float e = expf(s - m);
            float su = e;
#pragma unroll
            for (int o = 16; o; o >>= 1) su += __shfl_xor_sync(0xffffffffu, su, o);
            attn = e / su;    // bl dropped: softmax-invariant
        }

        // ---- output: out[n,d] = sum_k attn[k] * x_nb[n,k,d]  (fp32, L1-hot) ----
        {
            const int node = w >> 2;                 // warps 0-3 node0, 4-7 node1
            const int d = (w & 3) * 32 + lane;       // = tid & 127
            const long gn = (long)t * 2 + node;
            if (gn < N) {
                const float* src = x_nb + (gn * 32) * 128 + d;
                float s0 = 0.f, s1 = 0.f;
#pragma unroll
                for (int k = 0; k < 32; k += 2) {
                    const float a0 = __shfl_sync(0xffffffffu, attn, k);
                    const float a1 = __shfl_sync(0xffffffffu, attn, k + 1);
                    s0 = fmaf(a0, __ldg(src + k * 128), s0);
                    s1 = fmaf(a1, __ldg(src + (k + 1) * 128), s1);
                }
                out[gn * 128 + d] = s0 + s1;
            }
        }
    }
}

// ---------------------------------------------------------------------------
extern "C" void kernel_launch(void* const* d_in, const int* in_sizes, int n_in,
                              void* d_out, int out_size)
{
    const float* x      = (const float*)d_in[0];
    const float* x_nb   = (const float*)d_in[1];
    const float* weight = (const float*)d_in[2];
    const float* Wx     = (const float*)d_in[3];
    const float* bx     = (const float*)d_in[4];
    const float* Wn     = (const float*)d_in[5];
    const float* bn     = (const float*)d_in[6];
    const float* Ww     = (const float*)d_in[7];
    const float* bw     = (const float*)d_in[8];
    const float* Wl     = (const float*)d_in[9];
    // d_in[10] = bl: softmax-invariant, unused.
    float* out = (float*)d_out;

    const int N = in_sizes[0] / 128;

    const size_t smem1 = (size_t)(2 * 128 * STX + 128) * sizeof(float);
    cudaFuncSetAttribute(xs_kernel, cudaFuncAttributeMaxDynamicSharedMemorySize, (int)smem1);

    int nSM = 148;
    cudaDeviceGetAttribute(&nSM, cudaDevAttrMultiProcessorCount, 0);

    const int blocks1 = (N + 127) / 128;
    xs_kernel<<<blocks1, 256, smem1>>>(x, Wx, bx, N);

    const int numTiles = (N + 1) / 2;
    int grid = 2 * nSM;
    if (grid > numTiles) grid = numTiles;
    gnn_main_kernel<<<grid, 256>>>(x_nb, weight, Wn, bn, Ww, bw, Wl, out, N, numTiles);
}